// round 15
// baseline (speedup 1.0000x reference)
#include <cuda_runtime.h>
#include <math.h>

#define BB 16
#define NN 8192
#define CC 64
#define KK 128
#define K2 256
#define KW 320
#define RR 4
#define NL 4
#define NCHUNK 16
#define INVN (1.0f/8192.0f)

// exact gelu via erff (polynomial, no MUFU): x*Phi(x) = 0.5x(1+erf(x/sqrt2))
#define GELU(x) (0.5f * (x) * (1.0f + erff(0.7071067811865476f * (x))))

// packed fp32x2 helpers (sm_103a)
#define FMA2(acc, a, b) asm("fma.rn.f32x2 %0, %1, %2, %0;" : "+l"(acc) : "l"(a), "l"(b))
#define PACKF2(out, lo, hi) asm("mov.b64 %0, {%1, %2};" : "=l"(out) : "f"(lo), "f"(hi))
#define UNPACKF2(lo, hi, in) asm("mov.b64 {%0, %1}, %2;" : "=f"(lo), "=f"(hi) : "l"(in))

#define CP16(dst_u32, src) \
    asm volatile("cp.async.cg.shared.global [%0], [%1], 16;\n" :: "r"(dst_u32), "l"(src))
#define CP_COMMIT() asm volatile("cp.async.commit_group;\n")
#define CP_WAIT0()  asm volatile("cp.async.wait_group 0;\n" ::: "memory")

__device__ __forceinline__ unsigned smem_u32(const void* p) {
    return (unsigned)__cvta_generic_to_shared(p);
}

// Z layout per batch: rows 0..127 = cos bases*mask, 128..255 = sin bases*mask,
// rows 256..319 = current h (updated in place each layer).
__device__ float g_Z[(size_t)BB*KW*NN];          // ~168 MB
__device__ float g_ZT[(size_t)BB*NN*K2];         // bases transposed [b][n][k2]
__device__ float g_X2p[(size_t)BB*NCHUNK*CC*K2]; // forward split-K partials
__device__ float g_W[BB*CC*K2];                  // [2*f_c | -2*f_s]
__device__ float g_x0pA[BB*32*CC];               // x0 partials, double-buffered
__device__ float g_x0pB[BB*32*CC];
__device__ float g_wsz[BB*NN];
__device__ float g_mask[BB*NN];
__device__ float g_mw[BB*NN];

// ---------------------------------------------------------------------------
// Precompute: h0 = fc0(x), bases via complex recurrence
// ---------------------------------------------------------------------------
__global__ void __launch_bounds__(256) k_pre(const float* __restrict__ x,
                                             const float* __restrict__ fc0w,
                                             const float* __restrict__ fc0b) {
    int idx = blockIdx.x * blockDim.x + threadIdx.x;
    int b = idx >> 13, n = idx & (NN - 1);
    const float* xp = x + (size_t)idx * 7;
    float f0 = xp[0], f1 = xp[1], f2 = xp[2];
    float gx = xp[3], gy = xp[4], w = xp[5], m = xp[6];
    float wsz = w * (float)NN;
    g_wsz[idx]  = wsz;
    g_mask[idx] = m;
    g_mw[idx]   = m * wsz;

    float* Zb = g_Z + (size_t)b * KW * NN;
    #pragma unroll
    for (int c = 0; c < CC; c++) {
        float h = fc0b[c] + f0 * fc0w[c] + f1 * fc0w[CC + c] + f2 * fc0w[2 * CC + c];
        Zb[(size_t)(K2 + c) * NN + n] = h;
    }

    const float TWO_PI = 6.283185307179586f;
    float c1x, s1x, c1y, s1y;
    sincosf(TWO_PI * gx, &s1x, &c1x);
    sincosf(TWO_PI * gy, &s1y, &c1y);
    float cx[16], sx[16], cy[8], sy[8];
    cx[0] = 1.f; sx[0] = 0.f;
    #pragma unroll
    for (int j = 1; j < 16; j++) {
        cx[j] = cx[j-1]*c1x - sx[j-1]*s1x;
        sx[j] = sx[j-1]*c1x + cx[j-1]*s1x;
    }
    cy[0] = 1.f; sy[0] = 0.f;
    #pragma unroll
    for (int j = 1; j < 8; j++) {
        cy[j] = cy[j-1]*c1y - sy[j-1]*s1y;
        sy[j] = sy[j-1]*c1y + cy[j-1]*s1y;
    }
    #pragma unroll 8
    for (int k = 0; k < KK; k++) {
        int kxi = k >> 3, kyi = k & 7;
        float ck = cx[kxi]*cy[kyi] - sx[kxi]*sy[kyi];
        float sk = sx[kxi]*cy[kyi] + cx[kxi]*sy[kyi];
        Zb[(size_t)k * NN + n]        = ck * m;
        Zb[(size_t)(KK + k) * NN + n] = sk * m;
    }
}

// Transpose bases: g_ZT[b][n][k2] = g_Z[b][k2][n].
__global__ void __launch_bounds__(256) k_tr() {
    __shared__ float tile[32][33];
    int b = blockIdx.z;
    int n0 = blockIdx.x * 32, k0 = blockIdx.y * 32;
    int tx = threadIdx.x & 31, ty = threadIdx.x >> 5;
    const float* Zb = g_Z + (size_t)b * KW * NN;
    #pragma unroll
    for (int j = 0; j < 4; j++)
        tile[ty + 8*j][tx] = Zb[(size_t)(k0 + ty + 8*j) * NN + n0 + tx];
    __syncthreads();
    float* ZT = g_ZT + (size_t)b * NN * K2;
    #pragma unroll
    for (int j = 0; j < 4; j++)
        ZT[(size_t)(n0 + ty + 8*j) * K2 + k0 + tx] = tile[tx][ty + 8*j];
}

// Layer-0 x0 partials into buffer A: g_x0pA[b][chunk32][c] = sum_{n in 256-chunk} h*mw
__global__ void __launch_bounds__(256) k_x0p32() {
    int chunk = blockIdx.x, b = blockIdx.y;   // grid (32, BB)
    int w = threadIdx.x >> 5, lid = threadIdx.x & 31;
    const float* mw = g_mw + b * NN + chunk * 256;
    #pragma unroll
    for (int j = 0; j < 8; j++) {
        int c = w * 8 + j;
        const float* h = g_Z + (size_t)b * KW * NN + (size_t)(K2 + c) * NN + chunk * 256;
        float s = 0.f;
        #pragma unroll
        for (int i = 0; i < 8; i++)
            s += h[lid + i * 32] * mw[lid + i * 32];
        #pragma unroll
        for (int o = 16; o > 0; o >>= 1) s += __shfl_down_sync(0xffffffffu, s, o);
        if (lid == 0) g_x0pA[(b * 32 + chunk) * CC + c] = s;
    }
}

// ---------------------------------------------------------------------------
// Forward transform: partial X2[b][c][k2] = sum_n h*wsz*base
// Tile 64c x 256k2, n-chunk 512, kstep 32. Double-buffered (halved barriers).
// ---------------------------------------------------------------------------
__global__ void __launch_bounds__(256, 2) k_fwd() {
    int chunk = blockIdx.x, b = blockIdx.y;
    const float* Zb = g_Z + (size_t)b * KW * NN;
    const float* ZT = g_ZT + (size_t)b * NN * K2;
    const float* wszb = g_wsz + b * NN;
    __shared__ float Bs[2][32][256];
    __shared__ float Hs[2][32][128];
    int t = threadIdx.x;
    int ty = t >> 5, tx = t & 31;
    int c_ = t >> 2, nj_ = (t & 3) * 4;
    int sw = nj_ << 2;
    unsigned long long acc[8][4];
    #pragma unroll
    for (int u = 0; u < 8; u++)
        #pragma unroll
        for (int v = 0; v < 4; v++) acc[u][v] = 0ULL;

    int n0 = chunk * (NN / NCHUNK);
    float4 hv0, wv0, hv1, wv1;

    #define ISSUE_B(it_, s_) do {                                              \
        int nb_ = n0 + (it_) * 32;                                             \
        _Pragma("unroll")                                                      \
        for (int i_ = 0; i_ < 8; i_++) {                                       \
            int idx_ = t + i_ * 256;                                           \
            int nn_ = idx_ >> 6, k4_ = (idx_ & 63) * 4;                        \
            CP16(smem_u32(&Bs[s_][nn_][k4_]),                                  \
                 &ZT[(size_t)(nb_ + nn_) * K2 + k4_]);                         \
        }                                                                      \
        CP_COMMIT();                                                           \
    } while (0)

    #define LD_H(it_) do {                                                     \
        int nb_ = n0 + (it_) * 32;                                             \
        hv0 = *(const float4*)&Zb[(size_t)(K2 + c_) * NN + nb_ + nj_];         \
        wv0 = *(const float4*)&wszb[nb_ + nj_];                                \
        hv1 = *(const float4*)&Zb[(size_t)(K2 + c_) * NN + nb_ + nj_ + 16];    \
        wv1 = *(const float4*)&wszb[nb_ + nj_ + 16];                           \
    } while (0)

    #define ST_H(s_) do {                                                      \
        int col_ = (2 * c_) ^ sw;                                              \
        float a0_ = hv0.x*wv0.x, a1_ = hv0.y*wv0.y, a2_ = hv0.z*wv0.z, a3_ = hv0.w*wv0.w; \
        float a4_ = hv1.x*wv1.x, a5_ = hv1.y*wv1.y, a6_ = hv1.z*wv1.z, a7_ = hv1.w*wv1.w; \
        *(float2*)&Hs[s_][nj_+0][col_]  = make_float2(a0_, a0_);               \
        *(float2*)&Hs[s_][nj_+1][col_]  = make_float2(a1_, a1_);               \
        *(float2*)&Hs[s_][nj_+2][col_]  = make_float2(a2_, a2_);               \
        *(float2*)&Hs[s_][nj_+3][col_]  = make_float2(a3_, a3_);               \
        *(float2*)&Hs[s_][nj_+16][col_] = make_float2(a4_, a4_);               \
        *(float2*)&Hs[s_][nj_+17][col_] = make_float2(a5_, a5_);               \
        *(float2*)&Hs[s_][nj_+18][col_] = make_float2(a6_, a6_);               \
        *(float2*)&Hs[s_][nj_+19][col_] = make_float2(a7_, a7_);               \
    } while (0)

    ISSUE_B(0, 0);
    LD_H(0);
    ST_H(0);
    LD_H(1);
    CP_WAIT0();
    __syncthreads();

    for (int it = 0; it < 16; it++) {
        int sb = it & 1, sn = sb ^ 1;
        if (it < 15) { ISSUE_B(it + 1, sn); ST_H(sn); }
        #pragma unroll
        for (int nn = 0; nn < 32; nn++) {
            int swr = ((nn & 15) >> 2) << 4;
            int ca = (ty * 8) ^ swr;
            ulonglong2 a0 = *(const ulonglong2*)&Hs[sb][nn][ca];
            ulonglong2 a1 = *(const ulonglong2*)&Hs[sb][nn][ca + 4];
            ulonglong2 a2 = *(const ulonglong2*)&Hs[sb][nn][64 + ca];
            ulonglong2 a3 = *(const ulonglong2*)&Hs[sb][nn][64 + ca + 4];
            ulonglong2 b0 = *(const ulonglong2*)&Bs[sb][nn][tx*4];
            ulonglong2 b1 = *(const ulonglong2*)&Bs[sb][nn][128 + tx*4];
            unsigned long long av[8] = {a0.x, a0.y, a1.x, a1.y, a2.x, a2.y, a3.x, a3.y};
            unsigned long long bv[4] = {b0.x, b0.y, b1.x, b1.y};
            #pragma unroll
            for (int u = 0; u < 8; u++)
                #pragma unroll
                for (int v = 0; v < 4; v++)
                    FMA2(acc[u][v], av[u], bv[v]);
        }
        if (it < 14) LD_H(it + 2);
        if (it < 15) CP_WAIT0();
        __syncthreads();
    }
    #undef ISSUE_B
    #undef LD_H
    #undef ST_H

    float* P = g_X2p + (size_t)(b * NCHUNK + chunk) * CC * K2;
    #pragma unroll
    for (int u = 0; u < 8; u++) {
        int cu = (u < 4) ? (ty * 4 + u) : (32 + ty * 4 + u - 4);
        ulonglong2 s0; s0.x = acc[u][0]; s0.y = acc[u][1];
        ulonglong2 s1; s1.x = acc[u][2]; s1.y = acc[u][3];
        *(ulonglong2*)&P[cu * K2 + tx * 4]       = s0;
        *(ulonglong2*)&P[cu * K2 + 128 + tx * 4] = s1;
    }
}

// ---------------------------------------------------------------------------
// Low-rank mixing fused with split-K reduction — k-contiguous (coalesced).
// Grid (4 k-tiles of 32, BB), 256 threads.
// ---------------------------------------------------------------------------
__global__ void __launch_bounds__(256) k_lowrank(const float* __restrict__ wc1,
                                                 const float* __restrict__ wc2,
                                                 const float* __restrict__ ws1,
                                                 const float* __restrict__ ws2, int l) {
    int kt = blockIdx.x, b = blockIdx.y;
    int k0 = kt * 32;
    __shared__ float xc[CC][33];
    __shared__ float xs[CC][33];
    __shared__ float su[16][32];
    int t = threadIdx.x;
    int w = t >> 5, lane = t & 31;
    const float* P = g_X2p + (size_t)b * NCHUNK * CC * K2;

    // split-K reduction, coalesced: warp w handles o = j*8 + w
    #pragma unroll
    for (int j = 0; j < 8; j++) {
        int o = j * 8 + w;
        float sc = 0.f, ss = 0.f;
        #pragma unroll
        for (int ch = 0; ch < NCHUNK; ch++) {
            const float* row = P + (size_t)ch * CC * K2 + o * K2;
            sc += row[k0 + lane];
            ss += row[KK + k0 + lane];
        }
        xc[o][lane] = sc;
        xs[o][lane] = -ss;
    }
    __syncthreads();

    // u[which][r] per k: 16 combos x 32 k; each thread does 2 combos
    #pragma unroll
    for (int half = 0; half < 2; half++) {
        int combo = half * 8 + w;          // 0..15
        int which = combo >> 2, r = combo & 3;
        const float (*src)[33] = (which >> 1) ? xs : xc;
        const float* W1 = ((which & 1) ? ws1 : wc1) + (size_t)l * CC * RR * KK;
        float s = 0.f;
        #pragma unroll 8
        for (int i = 0; i < CC; i++)
            s += src[i][lane] * W1[(i * RR + r) * KK + k0 + lane];
        su[combo][lane] = s;
    }
    __syncthreads();

    // outputs, coalesced in k
    #pragma unroll
    for (int j = 0; j < 8; j++) {
        int o = j * 8 + w;
        float fc = 0.f, fs = 0.f;
        #pragma unroll
        for (int r = 0; r < RR; r++) {
            float c2v = wc2[((size_t)(l * RR + r) * CC + o) * KK + k0 + lane];
            float s2v = ws2[((size_t)(l * RR + r) * CC + o) * KK + k0 + lane];
            fc += su[r][lane]      * c2v - su[12 + r][lane] * s2v;
            fs += su[8 + r][lane]  * c2v + su[4 + r][lane]  * s2v;
        }
        g_W[(b * CC + o) * K2 + k0 + lane]      =  2.f * INVN * fc;
        g_W[(b * CC + o) * K2 + KK + k0 + lane] = -2.f * INVN * fs;
    }
}

// ---------------------------------------------------------------------------
// Inverse transform + conv + bias (+gelu) + inline f0 + next-layer x0 partials
// Tile 64c x 256n, kstep 32 (10 tiles). Double-buffered (halved barriers).
// ---------------------------------------------------------------------------
__global__ void __launch_bounds__(256, 2) k_inv(const float* __restrict__ wconv,
                                                const float* __restrict__ bconv,
                                                const float* __restrict__ w01,
                                                const float* __restrict__ w02,
                                                int l, int do_gelu) {
    int nt = blockIdx.x, b = blockIdx.y;
    int n0 = nt * 256;
    float* Zb = g_Z + (size_t)b * KW * NN;
    const float* Wb = g_W + (size_t)b * CC * K2;
    const float* wcv = wconv + l * CC * CC;
    const float* xin  = (l & 1) ? g_x0pB : g_x0pA;
    float*       xout = (l & 1) ? g_x0pA : g_x0pB;
    __shared__ float Zs[2][32][256];
    __shared__ float Ws[2][32][128];
    __shared__ float s_x0[CC];
    __shared__ float s_f0[CC];
    int t = threadIdx.x;
    int ty = t >> 5, tx = t & 31;
    int c_ = t >> 2, kj_ = (t & 3) * 4;
    int sw = kj_ << 2;
    unsigned long long acc[8][4];
    #pragma unroll
    for (int u = 0; u < 8; u++)
        #pragma unroll
        for (int v = 0; v < 4; v++) acc[u][v] = 0ULL;

    float w0, w1, w2, w3, w4, w5, w6, w7;

    #define ISSUE_Z(it_, s_) do {                                              \
        int k0_ = (it_) * 32;                                                  \
        _Pragma("unroll")                                                      \
        for (int i_ = 0; i_ < 8; i_++) {                                       \
            int idx_ = t + i_ * 256;                                           \
            int kk_ = idx_ >> 6, nl_ = (idx_ & 63) * 4;                        \
            CP16(smem_u32(&Zs[s_][kk_][nl_]),                                  \
                 &Zb[(size_t)(k0_ + kk_) * NN + n0 + nl_]);                    \
        }                                                                      \
        CP_COMMIT();                                                           \
    } while (0)

    #define LD_W(it_) do {                                                     \
        int k0_ = (it_) * 32;                                                  \
        if (k0_ < K2) {                                                        \
            float4 wa_ = *(const float4*)&Wb[c_ * K2 + k0_ + kj_];             \
            float4 wb_ = *(const float4*)&Wb[c_ * K2 + k0_ + kj_ + 16];        \
            w0 = wa_.x; w1 = wa_.y; w2 = wa_.z; w3 = wa_.w;                    \
            w4 = wb_.x; w5 = wb_.y; w6 = wb_.z; w7 = wb_.w;                    \
        } else {                                                               \
            int kq_ = k0_ + kj_ - K2;                                          \
            w0 = wcv[(kq_+0)  * CC + c_];                                      \
            w1 = wcv[(kq_+1)  * CC + c_];                                      \
            w2 = wcv[(kq_+2)  * CC + c_];                                      \
            w3 = wcv[(kq_+3)  * CC + c_];                                      \
            w4 = wcv[(kq_+16) * CC + c_];                                      \
            w5 = wcv[(kq_+17) * CC + c_];                                      \
            w6 = wcv[(kq_+18) * CC + c_];                                      \
            w7 = wcv[(kq_+19) * CC + c_];                                      \
        }                                                                      \
    } while (0)

    #define ST_W(s_) do {                                                      \
        int col_ = (2 * c_) ^ sw;                                              \
        *(float2*)&Ws[s_][kj_+0][col_]  = make_float2(w0, w0);                 \
        *(float2*)&Ws[s_][kj_+1][col_]  = make_float2(w1, w1);                 \
        *(float2*)&Ws[s_][kj_+2][col_]  = make_float2(w2, w2);                 \
        *(float2*)&Ws[s_][kj_+3][col_]  = make_float2(w3, w3);                 \
        *(float2*)&Ws[s_][kj_+16][col_] = make_float2(w4, w4);                 \
        *(float2*)&Ws[s_][kj_+17][col_] = make_float2(w5, w5);                 \
        *(float2*)&Ws[s_][kj_+18][col_] = make_float2(w6, w6);                 \
        *(float2*)&Ws[s_][kj_+19][col_] = make_float2(w7, w7);                 \
    } while (0)

    ISSUE_Z(0, 0);
    LD_W(0);
    ST_W(0);
    // phase A: x0[c] = sum of 32 partials (t < 64)
    if (t < CC) {
        float s = 0.f;
        #pragma unroll
        for (int ch = 0; ch < 32; ch++) s += xin[(b * 32 + ch) * CC + t];
        s_x0[t] = s;
    }
    LD_W(1);
    CP_WAIT0();
    __syncthreads();
    // phase B: f0[o] = rank-4 contraction of s_x0 (t < 64); visible after next bar
    if (t < CC) {
        float f = 0.f;
        #pragma unroll
        for (int r = 0; r < RR; r++) {
            float uu = 0.f;
            #pragma unroll 8
            for (int i = 0; i < CC; i++) uu += s_x0[i] * w01[(l * CC + i) * RR + r];
            f += uu * w02[(l * RR + r) * CC + t];
        }
        s_f0[t] = f * INVN;
    }

    for (int it = 0; it < 10; it++) {
        int sb = it & 1, sn = sb ^ 1;
        if (it < 9) { ISSUE_Z(it + 1, sn); ST_W(sn); }
        #pragma unroll
        for (int kk = 0; kk < 32; kk++) {
            int swr = ((kk & 15) >> 2) << 4;
            int ca = (ty * 8) ^ swr;
            ulonglong2 a0 = *(const ulonglong2*)&Ws[sb][kk][ca];
            ulonglong2 a1 = *(const ulonglong2*)&Ws[sb][kk][ca + 4];
            ulonglong2 a2 = *(const ulonglong2*)&Ws[sb][kk][64 + ca];
            ulonglong2 a3 = *(const ulonglong2*)&Ws[sb][kk][64 + ca + 4];
            ulonglong2 b0 = *(const ulonglong2*)&Zs[sb][kk][tx*4];
            ulonglong2 b1 = *(const ulonglong2*)&Zs[sb][kk][128 + tx*4];
            unsigned long long av[8] = {a0.x, a0.y, a1.x, a1.y, a2.x, a2.y, a3.x, a3.y};
            unsigned long long bv[4] = {b0.x, b0.y, b1.x, b1.y};
            #pragma unroll
            for (int u = 0; u < 8; u++)
                #pragma unroll
                for (int v = 0; v < 4; v++)
                    FMA2(acc[u][v], av[u], bv[v]);
        }
        if (it < 8) LD_W(it + 2);
        if (it < 9) CP_WAIT0();
        __syncthreads();
    }
    #undef ISSUE_Z
    #undef LD_W
    #undef ST_W

    float4 mk4[2], mw4[2];
    #pragma unroll
    for (int half = 0; half < 2; half++) {
        int nb = n0 + half * 128 + tx * 4;
        mk4[half] = *(const float4*)&g_mask[b * NN + nb];
        mw4[half] = *(const float4*)&g_mw[b * NN + nb];
    }
    float p[8];
    #pragma unroll
    for (int u = 0; u < 8; u++) p[u] = 0.f;
    #pragma unroll
    for (int u = 0; u < 8; u++) {
        int c = (u < 4) ? (ty * 4 + u) : (32 + ty * 4 + u - 4);
        float f0v = s_f0[c];
        float bcv = bconv[l * CC + c];
        float ov[8];
        #pragma unroll
        for (int v = 0; v < 4; v++) {
            float lo, hi;
            UNPACKF2(lo, hi, acc[u][v]);
            ov[2*v] = lo; ov[2*v+1] = hi;
        }
        #pragma unroll
        for (int half = 0; half < 2; half++) {
            int nb = n0 + half * 128 + tx * 4;
            const float* mkp = (const float*)&mk4[half];
            const float* mwp = (const float*)&mw4[half];
            float r[4];
            #pragma unroll
            for (int j = 0; j < 4; j++) {
                float val = ov[half*4 + j] + f0v * mkp[j] + bcv;
                if (do_gelu) val = GELU(val);
                r[j] = val;
                p[u] += val * mwp[j];
            }
            *(float4*)&Zb[(size_t)(K2 + c) * NN + nb] = make_float4(r[0], r[1], r[2], r[3]);
        }
    }
    if (do_gelu) {
        #pragma unroll
        for (int u = 0; u < 8; u++) {
            float s = p[u];
            #pragma unroll
            for (int o = 16; o > 0; o >>= 1) s += __shfl_down_sync(0xffffffffu, s, o);
            if (tx == 0) {
                int c = (u < 4) ? (ty * 4 + u) : (32 + ty * 4 + u - 4);
                xout[(b * 32 + nt) * CC + c] = s;
            }
        }
    }
}

// Final MLP: out = fc2(gelu(fc1(h)))
__global__ void __launch_bounds__(256) k_mlp(const float* __restrict__ w1,
                                             const float* __restrict__ b1,
                                             const float* __restrict__ w2,
                                             const float* __restrict__ b2,
                                             float* __restrict__ out) {
    __shared__ float Wsm[CC * 128];
    __shared__ float b1s[128], w2s[128];
    int t = threadIdx.x;
    for (int i = t; i < CC * 128; i += 256) Wsm[i] = w1[i];
    if (t < 128) { b1s[t] = b1[t]; w2s[t] = w2[t]; }
    __syncthreads();
    int b = blockIdx.y;
    int n = blockIdx.x * 256 + t;
    const float* Zb = g_Z + (size_t)b * KW * NN;
    float h[CC];
    #pragma unroll
    for (int c = 0; c < CC; c++) h[c] = Zb[(size_t)(K2 + c) * NN + n];
    float acc = b2[0];
    for (int j0 = 0; j0 < 128; j0 += 8) {
        unsigned long long a[4];
        PACKF2(a[0], b1s[j0+0], b1s[j0+1]);
        PACKF2(a[1], b1s[j0+2], b1s[j0+3]);
        PACKF2(a[2], b1s[j0+4], b1s[j0+5]);
        PACKF2(a[3], b1s[j0+6], b1s[j0+7]);
        #pragma unroll
        for (int c = 0; c < CC; c++) {
            unsigned long long hd;
            PACKF2(hd, h[c], h[c]);
            ulonglong2 w0v = *(const ulonglong2*)&Wsm[c * 128 + j0];
            ulonglong2 w1v = *(const ulonglong2*)&Wsm[c * 128 + j0 + 4];
            FMA2(a[0], hd, w0v.x);
            FMA2(a[1], hd, w0v.y);
            FMA2(a[2], hd, w1v.x);
            FMA2(a[3], hd, w1v.y);
        }
        #pragma unroll
        for (int p = 0; p < 4; p++) {
            float lo, hi;
            UNPACKF2(lo, hi, a[p]);
            acc += GELU(lo) * w2s[j0 + 2*p];
            acc += GELU(hi) * w2s[j0 + 2*p + 1];
        }
    }
    out[(size_t)b * NN + n] = acc;
}

extern "C" void kernel_launch(void* const* d_in, const int* in_sizes, int n_in,
                              void* d_out, int out_size) {
    const float* x    = (const float*)d_in[0];
    const float* fc0w = (const float*)d_in[1];
    const float* fc0b = (const float*)d_in[2];
    const float* wc1  = (const float*)d_in[3];
    const float* wc2  = (const float*)d_in[4];
    const float* ws1  = (const float*)d_in[5];
    const float* ws2  = (const float*)d_in[6];
    const float* w01  = (const float*)d_in[7];
    const float* w02  = (const float*)d_in[8];
    const float* wconv = (const float*)d_in[9];
    const float* bconv = (const float*)d_in[10];
    const float* fc1w = (const float*)d_in[11];
    const float* fc1b = (const float*)d_in[12];
    const float* fc2w = (const float*)d_in[13];
    const float* fc2b = (const float*)d_in[14];
    float* out = (float*)d_out;

    k_pre<<<BB * NN / 256, 256>>>(x, fc0w, fc0b);
    k_tr<<<dim3(NN / 32, K2 / 32, BB), 256>>>();
    k_x0p32<<<dim3(32, BB), 256>>>();
    for (int l = 0; l < NL; l++) {
        k_fwd<<<dim3(NCHUNK, BB), 256>>>();
        k_lowrank<<<dim3(4, BB), 256>>>(wc1, wc2, ws1, ws2, l);
        k_inv<<<dim3(NN / 256, BB), 256>>>(wconv, bconv, w01, w02, l,
                                           (l != NL - 1) ? 1 : 0);
    }
    k_mlp<<<dim3(NN / 256, BB), 256>>>(fc1w, fc1b, fc2w, fc2b, out);
}

// round 16
// speedup vs baseline: 1.0032x; 1.0032x over previous
#include <cuda_runtime.h>
#include <math.h>

#define BB 16
#define NN 8192
#define CC 64
#define KK 128
#define K2 256
#define KW 320
#define RR 4
#define NL 4
#define NCHUNK 16
#define INVN (1.0f/8192.0f)

// exact gelu via erff (polynomial, no MUFU): x*Phi(x) = 0.5x(1+erf(x/sqrt2))
#define GELU(x) (0.5f * (x) * (1.0f + erff(0.7071067811865476f * (x))))

// packed fp32x2 helpers (sm_103a)
#define FMA2(acc, a, b) asm("fma.rn.f32x2 %0, %1, %2, %0;" : "+l"(acc) : "l"(a), "l"(b))
#define PACKF2(out, lo, hi) asm("mov.b64 %0, {%1, %2};" : "=l"(out) : "f"(lo), "f"(hi))
#define UNPACKF2(lo, hi, in) asm("mov.b64 {%0, %1}, %2;" : "=f"(lo), "=f"(hi) : "l"(in))

#define CP16(dst_u32, src) \
    asm volatile("cp.async.cg.shared.global [%0], [%1], 16;\n" :: "r"(dst_u32), "l"(src))
#define CP_COMMIT() asm volatile("cp.async.commit_group;\n")
#define CP_WAIT0()  asm volatile("cp.async.wait_group 0;\n" ::: "memory")

__device__ __forceinline__ unsigned smem_u32(const void* p) {
    return (unsigned)__cvta_generic_to_shared(p);
}

// Z layout per batch: rows 0..127 = cos bases*mask, 128..255 = sin bases*mask,
// rows 256..319 = current h (updated in place each layer).
__device__ float g_Z[(size_t)BB*KW*NN];          // ~168 MB
__device__ float g_ZT[(size_t)BB*NN*K2];         // bases transposed [b][n][k2]
__device__ float g_X2p[(size_t)BB*NCHUNK*CC*K2]; // forward split-K partials
__device__ float g_W[BB*CC*K2];                  // [2*f_c | -2*f_s]
__device__ float g_x0pA[BB*32*CC];               // x0 partials, double-buffered
__device__ float g_x0pB[BB*32*CC];
__device__ float g_wsz[BB*NN];
__device__ float g_mask[BB*NN];
__device__ float g_mw[BB*NN];

// ---------------------------------------------------------------------------
// Precompute: h0 = fc0(x), bases via complex recurrence
// ---------------------------------------------------------------------------
__global__ void __launch_bounds__(256) k_pre(const float* __restrict__ x,
                                             const float* __restrict__ fc0w,
                                             const float* __restrict__ fc0b) {
    int idx = blockIdx.x * blockDim.x + threadIdx.x;
    int b = idx >> 13, n = idx & (NN - 1);
    const float* xp = x + (size_t)idx * 7;
    float f0 = xp[0], f1 = xp[1], f2 = xp[2];
    float gx = xp[3], gy = xp[4], w = xp[5], m = xp[6];
    float wsz = w * (float)NN;
    g_wsz[idx]  = wsz;
    g_mask[idx] = m;
    g_mw[idx]   = m * wsz;

    float* Zb = g_Z + (size_t)b * KW * NN;
    #pragma unroll
    for (int c = 0; c < CC; c++) {
        float h = fc0b[c] + f0 * fc0w[c] + f1 * fc0w[CC + c] + f2 * fc0w[2 * CC + c];
        Zb[(size_t)(K2 + c) * NN + n] = h;
    }

    const float TWO_PI = 6.283185307179586f;
    float c1x, s1x, c1y, s1y;
    sincosf(TWO_PI * gx, &s1x, &c1x);
    sincosf(TWO_PI * gy, &s1y, &c1y);
    float cx[16], sx[16], cy[8], sy[8];
    cx[0] = 1.f; sx[0] = 0.f;
    #pragma unroll
    for (int j = 1; j < 16; j++) {
        cx[j] = cx[j-1]*c1x - sx[j-1]*s1x;
        sx[j] = sx[j-1]*c1x + cx[j-1]*s1x;
    }
    cy[0] = 1.f; sy[0] = 0.f;
    #pragma unroll
    for (int j = 1; j < 8; j++) {
        cy[j] = cy[j-1]*c1y - sy[j-1]*s1y;
        sy[j] = sy[j-1]*c1y + cy[j-1]*s1y;
    }
    #pragma unroll 8
    for (int k = 0; k < KK; k++) {
        int kxi = k >> 3, kyi = k & 7;
        float ck = cx[kxi]*cy[kyi] - sx[kxi]*sy[kyi];
        float sk = sx[kxi]*cy[kyi] + cx[kxi]*sy[kyi];
        Zb[(size_t)k * NN + n]        = ck * m;
        Zb[(size_t)(KK + k) * NN + n] = sk * m;
    }
}

// Transpose bases: g_ZT[b][n][k2] = g_Z[b][k2][n].
__global__ void __launch_bounds__(256) k_tr() {
    __shared__ float tile[32][33];
    int b = blockIdx.z;
    int n0 = blockIdx.x * 32, k0 = blockIdx.y * 32;
    int tx = threadIdx.x & 31, ty = threadIdx.x >> 5;
    const float* Zb = g_Z + (size_t)b * KW * NN;
    #pragma unroll
    for (int j = 0; j < 4; j++)
        tile[ty + 8*j][tx] = Zb[(size_t)(k0 + ty + 8*j) * NN + n0 + tx];
    __syncthreads();
    float* ZT = g_ZT + (size_t)b * NN * K2;
    #pragma unroll
    for (int j = 0; j < 4; j++)
        ZT[(size_t)(n0 + ty + 8*j) * K2 + k0 + tx] = tile[tx][ty + 8*j];
}

// Layer-0 x0 partials into buffer A: g_x0pA[b][chunk32][c] = sum_{n in 256-chunk} h*mw
__global__ void __launch_bounds__(256) k_x0p32() {
    int chunk = blockIdx.x, b = blockIdx.y;   // grid (32, BB)
    int w = threadIdx.x >> 5, lid = threadIdx.x & 31;
    const float* mw = g_mw + b * NN + chunk * 256;
    #pragma unroll
    for (int j = 0; j < 8; j++) {
        int c = w * 8 + j;
        const float* h = g_Z + (size_t)b * KW * NN + (size_t)(K2 + c) * NN + chunk * 256;
        float s = 0.f;
        #pragma unroll
        for (int i = 0; i < 8; i++)
            s += h[lid + i * 32] * mw[lid + i * 32];
        #pragma unroll
        for (int o = 16; o > 0; o >>= 1) s += __shfl_down_sync(0xffffffffu, s, o);
        if (lid == 0) g_x0pA[(b * 32 + chunk) * CC + c] = s;
    }
}

// ---------------------------------------------------------------------------
// Forward transform: partial X2[b][c][k2] = sum_n h*wsz*base
// Tile 64c x 256k2, n-chunk 512, kstep 32. Double-buffered (halved barriers).
// ---------------------------------------------------------------------------
__global__ void __launch_bounds__(256, 2) k_fwd() {
    int chunk = blockIdx.x, b = blockIdx.y;
    const float* Zb = g_Z + (size_t)b * KW * NN;
    const float* ZT = g_ZT + (size_t)b * NN * K2;
    const float* wszb = g_wsz + b * NN;
    __shared__ float Bs[2][32][256];
    __shared__ float Hs[2][32][128];
    int t = threadIdx.x;
    int ty = t >> 5, tx = t & 31;
    int c_ = t >> 2, nj_ = (t & 3) * 4;
    int sw = nj_ << 2;
    unsigned long long acc[8][4];
    #pragma unroll
    for (int u = 0; u < 8; u++)
        #pragma unroll
        for (int v = 0; v < 4; v++) acc[u][v] = 0ULL;

    int n0 = chunk * (NN / NCHUNK);
    float4 hv0, wv0, hv1, wv1;

    #define ISSUE_B(it_, s_) do {                                              \
        int nb_ = n0 + (it_) * 32;                                             \
        _Pragma("unroll")                                                      \
        for (int i_ = 0; i_ < 8; i_++) {                                       \
            int idx_ = t + i_ * 256;                                           \
            int nn_ = idx_ >> 6, k4_ = (idx_ & 63) * 4;                        \
            CP16(smem_u32(&Bs[s_][nn_][k4_]),                                  \
                 &ZT[(size_t)(nb_ + nn_) * K2 + k4_]);                         \
        }                                                                      \
        CP_COMMIT();                                                           \
    } while (0)

    #define LD_H(it_) do {                                                     \
        int nb_ = n0 + (it_) * 32;                                             \
        hv0 = *(const float4*)&Zb[(size_t)(K2 + c_) * NN + nb_ + nj_];         \
        wv0 = *(const float4*)&wszb[nb_ + nj_];                                \
        hv1 = *(const float4*)&Zb[(size_t)(K2 + c_) * NN + nb_ + nj_ + 16];    \
        wv1 = *(const float4*)&wszb[nb_ + nj_ + 16];                           \
    } while (0)

    #define ST_H(s_) do {                                                      \
        int col_ = (2 * c_) ^ sw;                                              \
        float a0_ = hv0.x*wv0.x, a1_ = hv0.y*wv0.y, a2_ = hv0.z*wv0.z, a3_ = hv0.w*wv0.w; \
        float a4_ = hv1.x*wv1.x, a5_ = hv1.y*wv1.y, a6_ = hv1.z*wv1.z, a7_ = hv1.w*wv1.w; \
        *(float2*)&Hs[s_][nj_+0][col_]  = make_float2(a0_, a0_);               \
        *(float2*)&Hs[s_][nj_+1][col_]  = make_float2(a1_, a1_);               \
        *(float2*)&Hs[s_][nj_+2][col_]  = make_float2(a2_, a2_);               \
        *(float2*)&Hs[s_][nj_+3][col_]  = make_float2(a3_, a3_);               \
        *(float2*)&Hs[s_][nj_+16][col_] = make_float2(a4_, a4_);               \
        *(float2*)&Hs[s_][nj_+17][col_] = make_float2(a5_, a5_);               \
        *(float2*)&Hs[s_][nj_+18][col_] = make_float2(a6_, a6_);               \
        *(float2*)&Hs[s_][nj_+19][col_] = make_float2(a7_, a7_);               \
    } while (0)

    ISSUE_B(0, 0);
    LD_H(0);
    ST_H(0);
    LD_H(1);
    CP_WAIT0();
    __syncthreads();

    for (int it = 0; it < 16; it++) {
        int sb = it & 1, sn = sb ^ 1;
        if (it < 15) { ISSUE_B(it + 1, sn); ST_H(sn); }
        #pragma unroll
        for (int nn = 0; nn < 32; nn++) {
            int swr = ((nn & 15) >> 2) << 4;
            int ca = (ty * 8) ^ swr;
            ulonglong2 a0 = *(const ulonglong2*)&Hs[sb][nn][ca];
            ulonglong2 a1 = *(const ulonglong2*)&Hs[sb][nn][ca + 4];
            ulonglong2 a2 = *(const ulonglong2*)&Hs[sb][nn][64 + ca];
            ulonglong2 a3 = *(const ulonglong2*)&Hs[sb][nn][64 + ca + 4];
            ulonglong2 b0 = *(const ulonglong2*)&Bs[sb][nn][tx*4];
            ulonglong2 b1 = *(const ulonglong2*)&Bs[sb][nn][128 + tx*4];
            unsigned long long av[8] = {a0.x, a0.y, a1.x, a1.y, a2.x, a2.y, a3.x, a3.y};
            unsigned long long bv[4] = {b0.x, b0.y, b1.x, b1.y};
            #pragma unroll
            for (int u = 0; u < 8; u++)
                #pragma unroll
                for (int v = 0; v < 4; v++)
                    FMA2(acc[u][v], av[u], bv[v]);
        }
        if (it < 14) LD_H(it + 2);
        if (it < 15) CP_WAIT0();
        __syncthreads();
    }
    #undef ISSUE_B
    #undef LD_H
    #undef ST_H

    float* P = g_X2p + (size_t)(b * NCHUNK + chunk) * CC * K2;
    #pragma unroll
    for (int u = 0; u < 8; u++) {
        int cu = (u < 4) ? (ty * 4 + u) : (32 + ty * 4 + u - 4);
        ulonglong2 s0; s0.x = acc[u][0]; s0.y = acc[u][1];
        ulonglong2 s1; s1.x = acc[u][2]; s1.y = acc[u][3];
        *(ulonglong2*)&P[cu * K2 + tx * 4]       = s0;
        *(ulonglong2*)&P[cu * K2 + 128 + tx * 4] = s1;
    }
}

// ---------------------------------------------------------------------------
// Low-rank mixing fused with split-K reduction — k-contiguous (coalesced).
// Grid (4 k-tiles of 32, BB), 256 threads.
// ---------------------------------------------------------------------------
__global__ void __launch_bounds__(256) k_lowrank(const float* __restrict__ wc1,
                                                 const float* __restrict__ wc2,
                                                 const float* __restrict__ ws1,
                                                 const float* __restrict__ ws2, int l) {
    int kt = blockIdx.x, b = blockIdx.y;
    int k0 = kt * 32;
    __shared__ float xc[CC][33];
    __shared__ float xs[CC][33];
    __shared__ float su[16][32];
    int t = threadIdx.x;
    int w = t >> 5, lane = t & 31;
    const float* P = g_X2p + (size_t)b * NCHUNK * CC * K2;

    // split-K reduction, coalesced: warp w handles o = j*8 + w
    #pragma unroll
    for (int j = 0; j < 8; j++) {
        int o = j * 8 + w;
        float sc = 0.f, ss = 0.f;
        #pragma unroll
        for (int ch = 0; ch < NCHUNK; ch++) {
            const float* row = P + (size_t)ch * CC * K2 + o * K2;
            sc += row[k0 + lane];
            ss += row[KK + k0 + lane];
        }
        xc[o][lane] = sc;
        xs[o][lane] = -ss;
    }
    __syncthreads();

    // u[which][r] per k: 16 combos x 32 k; each thread does 2 combos
    #pragma unroll
    for (int half = 0; half < 2; half++) {
        int combo = half * 8 + w;          // 0..15
        int which = combo >> 2, r = combo & 3;
        const float (*src)[33] = (which >> 1) ? xs : xc;
        const float* W1 = ((which & 1) ? ws1 : wc1) + (size_t)l * CC * RR * KK;
        float s = 0.f;
        #pragma unroll 8
        for (int i = 0; i < CC; i++)
            s += src[i][lane] * W1[(i * RR + r) * KK + k0 + lane];
        su[combo][lane] = s;
    }
    __syncthreads();

    // outputs, coalesced in k
    #pragma unroll
    for (int j = 0; j < 8; j++) {
        int o = j * 8 + w;
        float fc = 0.f, fs = 0.f;
        #pragma unroll
        for (int r = 0; r < RR; r++) {
            float c2v = wc2[((size_t)(l * RR + r) * CC + o) * KK + k0 + lane];
            float s2v = ws2[((size_t)(l * RR + r) * CC + o) * KK + k0 + lane];
            fc += su[r][lane]      * c2v - su[12 + r][lane] * s2v;
            fs += su[8 + r][lane]  * c2v + su[4 + r][lane]  * s2v;
        }
        g_W[(b * CC + o) * K2 + k0 + lane]      =  2.f * INVN * fc;
        g_W[(b * CC + o) * K2 + KK + k0 + lane] = -2.f * INVN * fs;
    }
}

// ---------------------------------------------------------------------------
// Inverse transform + conv + bias (+gelu) + inline f0 + next-layer x0 partials
// Tile 64c x 256n, kstep 32 (10 tiles). Double-buffered (halved barriers).
// ---------------------------------------------------------------------------
__global__ void __launch_bounds__(256, 2) k_inv(const float* __restrict__ wconv,
                                                const float* __restrict__ bconv,
                                                const float* __restrict__ w01,
                                                const float* __restrict__ w02,
                                                int l, int do_gelu) {
    int nt = blockIdx.x, b = blockIdx.y;
    int n0 = nt * 256;
    float* Zb = g_Z + (size_t)b * KW * NN;
    const float* Wb = g_W + (size_t)b * CC * K2;
    const float* wcv = wconv + l * CC * CC;
    const float* xin  = (l & 1) ? g_x0pB : g_x0pA;
    float*       xout = (l & 1) ? g_x0pA : g_x0pB;
    __shared__ float Zs[2][32][256];
    __shared__ float Ws[2][32][128];
    __shared__ float s_x0[CC];
    __shared__ float s_f0[CC];
    int t = threadIdx.x;
    int ty = t >> 5, tx = t & 31;
    int c_ = t >> 2, kj_ = (t & 3) * 4;
    int sw = kj_ << 2;
    unsigned long long acc[8][4];
    #pragma unroll
    for (int u = 0; u < 8; u++)
        #pragma unroll
        for (int v = 0; v < 4; v++) acc[u][v] = 0ULL;

    float w0, w1, w2, w3, w4, w5, w6, w7;

    #define ISSUE_Z(it_, s_) do {                                              \
        int k0_ = (it_) * 32;                                                  \
        _Pragma("unroll")                                                      \
        for (int i_ = 0; i_ < 8; i_++) {                                       \
            int idx_ = t + i_ * 256;                                           \
            int kk_ = idx_ >> 6, nl_ = (idx_ & 63) * 4;                        \
            CP16(smem_u32(&Zs[s_][kk_][nl_]),                                  \
                 &Zb[(size_t)(k0_ + kk_) * NN + n0 + nl_]);                    \
        }                                                                      \
        CP_COMMIT();                                                           \
    } while (0)

    #define LD_W(it_) do {                                                     \
        int k0_ = (it_) * 32;                                                  \
        if (k0_ < K2) {                                                        \
            float4 wa_ = *(const float4*)&Wb[c_ * K2 + k0_ + kj_];             \
            float4 wb_ = *(const float4*)&Wb[c_ * K2 + k0_ + kj_ + 16];        \
            w0 = wa_.x; w1 = wa_.y; w2 = wa_.z; w3 = wa_.w;                    \
            w4 = wb_.x; w5 = wb_.y; w6 = wb_.z; w7 = wb_.w;                    \
        } else {                                                               \
            int kq_ = k0_ + kj_ - K2;                                          \
            w0 = wcv[(kq_+0)  * CC + c_];                                      \
            w1 = wcv[(kq_+1)  * CC + c_];                                      \
            w2 = wcv[(kq_+2)  * CC + c_];                                      \
            w3 = wcv[(kq_+3)  * CC + c_];                                      \
            w4 = wcv[(kq_+16) * CC + c_];                                      \
            w5 = wcv[(kq_+17) * CC + c_];                                      \
            w6 = wcv[(kq_+18) * CC + c_];                                      \
            w7 = wcv[(kq_+19) * CC + c_];                                      \
        }                                                                      \
    } while (0)

    #define ST_W(s_) do {                                                      \
        int col_ = (2 * c_) ^ sw;                                              \
        *(float2*)&Ws[s_][kj_+0][col_]  = make_float2(w0, w0);                 \
        *(float2*)&Ws[s_][kj_+1][col_]  = make_float2(w1, w1);                 \
        *(float2*)&Ws[s_][kj_+2][col_]  = make_float2(w2, w2);                 \
        *(float2*)&Ws[s_][kj_+3][col_]  = make_float2(w3, w3);                 \
        *(float2*)&Ws[s_][kj_+16][col_] = make_float2(w4, w4);                 \
        *(float2*)&Ws[s_][kj_+17][col_] = make_float2(w5, w5);                 \
        *(float2*)&Ws[s_][kj_+18][col_] = make_float2(w6, w6);                 \
        *(float2*)&Ws[s_][kj_+19][col_] = make_float2(w7, w7);                 \
    } while (0)

    ISSUE_Z(0, 0);
    LD_W(0);
    ST_W(0);
    // phase A: x0[c] = sum of 32 partials (t < 64)
    if (t < CC) {
        float s = 0.f;
        #pragma unroll
        for (int ch = 0; ch < 32; ch++) s += xin[(b * 32 + ch) * CC + t];
        s_x0[t] = s;
    }
    LD_W(1);
    CP_WAIT0();
    __syncthreads();
    // phase B: f0[o] = rank-4 contraction of s_x0 (t < 64); visible after next bar
    if (t < CC) {
        float f = 0.f;
        #pragma unroll
        for (int r = 0; r < RR; r++) {
            float uu = 0.f;
            #pragma unroll 8
            for (int i = 0; i < CC; i++) uu += s_x0[i] * w01[(l * CC + i) * RR + r];
            f += uu * w02[(l * RR + r) * CC + t];
        }
        s_f0[t] = f * INVN;
    }

    for (int it = 0; it < 10; it++) {
        int sb = it & 1, sn = sb ^ 1;
        if (it < 9) { ISSUE_Z(it + 1, sn); ST_W(sn); }
        #pragma unroll
        for (int kk = 0; kk < 32; kk++) {
            int swr = ((kk & 15) >> 2) << 4;
            int ca = (ty * 8) ^ swr;
            ulonglong2 a0 = *(const ulonglong2*)&Ws[sb][kk][ca];
            ulonglong2 a1 = *(const ulonglong2*)&Ws[sb][kk][ca + 4];
            ulonglong2 a2 = *(const ulonglong2*)&Ws[sb][kk][64 + ca];
            ulonglong2 a3 = *(const ulonglong2*)&Ws[sb][kk][64 + ca + 4];
            ulonglong2 b0 = *(const ulonglong2*)&Zs[sb][kk][tx*4];
            ulonglong2 b1 = *(const ulonglong2*)&Zs[sb][kk][128 + tx*4];
            unsigned long long av[8] = {a0.x, a0.y, a1.x, a1.y, a2.x, a2.y, a3.x, a3.y};
            unsigned long long bv[4] = {b0.x, b0.y, b1.x, b1.y};
            #pragma unroll
            for (int u = 0; u < 8; u++)
                #pragma unroll
                for (int v = 0; v < 4; v++)
                    FMA2(acc[u][v], av[u], bv[v]);
        }
        if (it < 8) LD_W(it + 2);
        if (it < 9) CP_WAIT0();
        __syncthreads();
    }
    #undef ISSUE_Z
    #undef LD_W
    #undef ST_W

    float4 mk4[2], mw4[2];
    #pragma unroll
    for (int half = 0; half < 2; half++) {
        int nb = n0 + half * 128 + tx * 4;
        mk4[half] = *(const float4*)&g_mask[b * NN + nb];
        mw4[half] = *(const float4*)&g_mw[b * NN + nb];
    }
    float p[8];
    #pragma unroll
    for (int u = 0; u < 8; u++) p[u] = 0.f;
    #pragma unroll
    for (int u = 0; u < 8; u++) {
        int c = (u < 4) ? (ty * 4 + u) : (32 + ty * 4 + u - 4);
        float f0v = s_f0[c];
        float bcv = bconv[l * CC + c];
        float ov[8];
        #pragma unroll
        for (int v = 0; v < 4; v++) {
            float lo, hi;
            UNPACKF2(lo, hi, acc[u][v]);
            ov[2*v] = lo; ov[2*v+1] = hi;
        }
        #pragma unroll
        for (int half = 0; half < 2; half++) {
            int nb = n0 + half * 128 + tx * 4;
            const float* mkp = (const float*)&mk4[half];
            const float* mwp = (const float*)&mw4[half];
            float r[4];
            #pragma unroll
            for (int j = 0; j < 4; j++) {
                float val = ov[half*4 + j] + f0v * mkp[j] + bcv;
                if (do_gelu) val = GELU(val);
                r[j] = val;
                p[u] += val * mwp[j];
            }
            *(float4*)&Zb[(size_t)(K2 + c) * NN + nb] = make_float4(r[0], r[1], r[2], r[3]);
        }
    }
    if (do_gelu) {
        #pragma unroll
        for (int u = 0; u < 8; u++) {
            float s = p[u];
            #pragma unroll
            for (int o = 16; o > 0; o >>= 1) s += __shfl_down_sync(0xffffffffu, s, o);
            if (tx == 0) {
                int c = (u < 4) ? (ty * 4 + u) : (32 + ty * 4 + u - 4);
                xout[(b * 32 + nt) * CC + c] = s;
            }
        }
    }
}

// Final MLP: out = fc2(gelu(fc1(h)))
__global__ void __launch_bounds__(256) k_mlp(const float* __restrict__ w1,
                                             const float* __restrict__ b1,
                                             const float* __restrict__ w2,
                                             const float* __restrict__ b2,
                                             float* __restrict__ out) {
    __shared__ float Wsm[CC * 128];
    __shared__ float b1s[128], w2s[128];
    int t = threadIdx.x;
    for (int i = t; i < CC * 128; i += 256) Wsm[i] = w1[i];
    if (t < 128) { b1s[t] = b1[t]; w2s[t] = w2[t]; }
    __syncthreads();
    int b = blockIdx.y;
    int n = blockIdx.x * 256 + t;
    const float* Zb = g_Z + (size_t)b * KW * NN;
    float h[CC];
    #pragma unroll
    for (int c = 0; c < CC; c++) h[c] = Zb[(size_t)(K2 + c) * NN + n];
    float acc = b2[0];
    for (int j0 = 0; j0 < 128; j0 += 8) {
        unsigned long long a[4];
        PACKF2(a[0], b1s[j0+0], b1s[j0+1]);
        PACKF2(a[1], b1s[j0+2], b1s[j0+3]);
        PACKF2(a[2], b1s[j0+4], b1s[j0+5]);
        PACKF2(a[3], b1s[j0+6], b1s[j0+7]);
        #pragma unroll
        for (int c = 0; c < CC; c++) {
            unsigned long long hd;
            PACKF2(hd, h[c], h[c]);
            ulonglong2 w0v = *(const ulonglong2*)&Wsm[c * 128 + j0];
            ulonglong2 w1v = *(const ulonglong2*)&Wsm[c * 128 + j0 + 4];
            FMA2(a[0], hd, w0v.x);
            FMA2(a[1], hd, w0v.y);
            FMA2(a[2], hd, w1v.x);
            FMA2(a[3], hd, w1v.y);
        }
        #pragma unroll
        for (int p = 0; p < 4; p++) {
            float lo, hi;
            UNPACKF2(lo, hi, a[p]);
            acc += GELU(lo) * w2s[j0 + 2*p];
            acc += GELU(hi) * w2s[j0 + 2*p + 1];
        }
    }
    out[(size_t)b * NN + n] = acc;
}

extern "C" void kernel_launch(void* const* d_in, const int* in_sizes, int n_in,
                              void* d_out, int out_size) {
    const float* x    = (const float*)d_in[0];
    const float* fc0w = (const float*)d_in[1];
    const float* fc0b = (const float*)d_in[2];
    const float* wc1  = (const float*)d_in[3];
    const float* wc2  = (const float*)d_in[4];
    const float* ws1  = (const float*)d_in[5];
    const float* ws2  = (const float*)d_in[6];
    const float* w01  = (const float*)d_in[7];
    const float* w02  = (const float*)d_in[8];
    const float* wconv = (const float*)d_in[9];
    const float* bconv = (const float*)d_in[10];
    const float* fc1w = (const float*)d_in[11];
    const float* fc1b = (const float*)d_in[12];
    const float* fc2w = (const float*)d_in[13];
    const float* fc2b = (const float*)d_in[14];
    float* out = (float*)d_out;

    k_pre<<<BB * NN / 256, 256>>>(x, fc0w, fc0b);
    k_tr<<<dim3(NN / 32, K2 / 32, BB), 256>>>();
    k_x0p32<<<dim3(32, BB), 256>>>();
    for (int l = 0; l < NL; l++) {
        k_fwd<<<dim3(NCHUNK, BB), 256>>>();
        k_lowrank<<<dim3(4, BB), 256>>>(wc1, wc2, ws1, ws2, l);
        k_inv<<<dim3(NN / 256, BB), 256>>>(wconv, bconv, w01, w02, l,
                                           (l != NL - 1) ? 1 : 0);
    }
    k_mlp<<<dim3(NN / 256, BB), 256>>>(fc1w, fc1b, fc2w, fc2b, out);
}

// round 17
// speedup vs baseline: 1.5582x; 1.5533x over previous
#include <cuda_runtime.h>
#include <math.h>

#define BB 16
#define NN 8192
#define CC 64
#define KK 128
#define K2 256
#define KW 320
#define RR 4
#define NL 4
#define NCHUNK 16
#define INVN (1.0f/8192.0f)

// exact gelu via erff (polynomial, no MUFU): x*Phi(x) = 0.5x(1+erf(x/sqrt2))
#define GELU(x) (0.5f * (x) * (1.0f + erff(0.7071067811865476f * (x))))

// packed fp32x2 helpers (sm_103a)
#define FMA2(acc, a, b) asm("fma.rn.f32x2 %0, %1, %2, %0;" : "+l"(acc) : "l"(a), "l"(b))
#define PACKF2(out, lo, hi) asm("mov.b64 %0, {%1, %2};" : "=l"(out) : "f"(lo), "f"(hi))
#define UNPACKF2(lo, hi, in) asm("mov.b64 {%0, %1}, %2;" : "=f"(lo), "=f"(hi) : "l"(in))

#define CP16(dst_u32, src) \
    asm volatile("cp.async.cg.shared.global [%0], [%1], 16;\n" :: "r"(dst_u32), "l"(src))
#define CP_COMMIT() asm volatile("cp.async.commit_group;\n")
#define CP_WAIT0()  asm volatile("cp.async.wait_group 0;\n" ::: "memory")

__device__ __forceinline__ unsigned smem_u32(const void* p) {
    return (unsigned)__cvta_generic_to_shared(p);
}

// Z layout per batch: rows 0..127 = cos bases*mask, 128..255 = sin bases*mask,
// rows 256..319 = current h (updated in place each layer).
__device__ float g_Z[(size_t)BB*KW*NN];          // ~168 MB
__device__ float g_ZT[(size_t)BB*NN*K2];         // bases transposed [b][n][k2]
__device__ float g_X2p[(size_t)BB*NCHUNK*CC*K2]; // forward split-K partials
__device__ float g_W[BB*CC*K2];                  // [2*f_c | -2*f_s]
__device__ float g_x0pA[BB*32*CC];               // x0 partials, double-buffered
__device__ float g_x0pB[BB*32*CC];
__device__ float g_wsz[BB*NN];
__device__ float g_mask[BB*NN];
__device__ float g_mw[BB*NN];

// ---------------------------------------------------------------------------
// Precompute: h0 = fc0(x), bases via complex recurrence
// ---------------------------------------------------------------------------
__global__ void __launch_bounds__(256) k_pre(const float* __restrict__ x,
                                             const float* __restrict__ fc0w,
                                             const float* __restrict__ fc0b) {
    int idx = blockIdx.x * blockDim.x + threadIdx.x;
    int b = idx >> 13, n = idx & (NN - 1);
    const float* xp = x + (size_t)idx * 7;
    float f0 = xp[0], f1 = xp[1], f2 = xp[2];
    float gx = xp[3], gy = xp[4], w = xp[5], m = xp[6];
    float wsz = w * (float)NN;
    g_wsz[idx]  = wsz;
    g_mask[idx] = m;
    g_mw[idx]   = m * wsz;

    float* Zb = g_Z + (size_t)b * KW * NN;
    #pragma unroll
    for (int c = 0; c < CC; c++) {
        float h = fc0b[c] + f0 * fc0w[c] + f1 * fc0w[CC + c] + f2 * fc0w[2 * CC + c];
        Zb[(size_t)(K2 + c) * NN + n] = h;
    }

    const float TWO_PI = 6.283185307179586f;
    float c1x, s1x, c1y, s1y;
    sincosf(TWO_PI * gx, &s1x, &c1x);
    sincosf(TWO_PI * gy, &s1y, &c1y);
    float cx[16], sx[16], cy[8], sy[8];
    cx[0] = 1.f; sx[0] = 0.f;
    #pragma unroll
    for (int j = 1; j < 16; j++) {
        cx[j] = cx[j-1]*c1x - sx[j-1]*s1x;
        sx[j] = sx[j-1]*c1x + cx[j-1]*s1x;
    }
    cy[0] = 1.f; sy[0] = 0.f;
    #pragma unroll
    for (int j = 1; j < 8; j++) {
        cy[j] = cy[j-1]*c1y - sy[j-1]*s1y;
        sy[j] = sy[j-1]*c1y + cy[j-1]*s1y;
    }
    #pragma unroll 8
    for (int k = 0; k < KK; k++) {
        int kxi = k >> 3, kyi = k & 7;
        float ck = cx[kxi]*cy[kyi] - sx[kxi]*sy[kyi];
        float sk = sx[kxi]*cy[kyi] + cx[kxi]*sy[kyi];
        Zb[(size_t)k * NN + n]        = ck * m;
        Zb[(size_t)(KK + k) * NN + n] = sk * m;
    }
}

// Transpose bases: g_ZT[b][n][k2] = g_Z[b][k2][n].
__global__ void __launch_bounds__(256) k_tr() {
    __shared__ float tile[32][33];
    int b = blockIdx.z;
    int n0 = blockIdx.x * 32, k0 = blockIdx.y * 32;
    int tx = threadIdx.x & 31, ty = threadIdx.x >> 5;
    const float* Zb = g_Z + (size_t)b * KW * NN;
    #pragma unroll
    for (int j = 0; j < 4; j++)
        tile[ty + 8*j][tx] = Zb[(size_t)(k0 + ty + 8*j) * NN + n0 + tx];
    __syncthreads();
    float* ZT = g_ZT + (size_t)b * NN * K2;
    #pragma unroll
    for (int j = 0; j < 4; j++)
        ZT[(size_t)(n0 + ty + 8*j) * K2 + k0 + tx] = tile[tx][ty + 8*j];
}

// Layer-0 x0 partials into buffer A: g_x0pA[b][chunk32][c] = sum_{n in 256-chunk} h*mw
__global__ void __launch_bounds__(256) k_x0p32() {
    int chunk = blockIdx.x, b = blockIdx.y;   // grid (32, BB)
    int w = threadIdx.x >> 5, lid = threadIdx.x & 31;
    const float* mw = g_mw + b * NN + chunk * 256;
    #pragma unroll
    for (int j = 0; j < 8; j++) {
        int c = w * 8 + j;
        const float* h = g_Z + (size_t)b * KW * NN + (size_t)(K2 + c) * NN + chunk * 256;
        float s = 0.f;
        #pragma unroll
        for (int i = 0; i < 8; i++)
            s += h[lid + i * 32] * mw[lid + i * 32];
        #pragma unroll
        for (int o = 16; o > 0; o >>= 1) s += __shfl_down_sync(0xffffffffu, s, o);
        if (lid == 0) g_x0pA[(b * 32 + chunk) * CC + c] = s;
    }
}

// ---------------------------------------------------------------------------
// Forward transform: partial X2[b][c][k2] = sum_n h*wsz*base
// Tile 64c x 256k2, n-chunk 512, kstep 32. Double-buffered (halved barriers).
// ---------------------------------------------------------------------------
__global__ void __launch_bounds__(256, 2) k_fwd() {
    int chunk = blockIdx.x, b = blockIdx.y;
    const float* Zb = g_Z + (size_t)b * KW * NN;
    const float* ZT = g_ZT + (size_t)b * NN * K2;
    const float* wszb = g_wsz + b * NN;
    __shared__ float Bs[2][32][256];
    __shared__ float Hs[2][32][128];
    int t = threadIdx.x;
    int ty = t >> 5, tx = t & 31;
    int c_ = t >> 2, nj_ = (t & 3) * 4;
    int sw = nj_ << 2;
    unsigned long long acc[8][4];
    #pragma unroll
    for (int u = 0; u < 8; u++)
        #pragma unroll
        for (int v = 0; v < 4; v++) acc[u][v] = 0ULL;

    int n0 = chunk * (NN / NCHUNK);
    float4 hv0, wv0, hv1, wv1;

    #define ISSUE_B(it_, s_) do {                                              \
        int nb_ = n0 + (it_) * 32;                                             \
        _Pragma("unroll")                                                      \
        for (int i_ = 0; i_ < 8; i_++) {                                       \
            int idx_ = t + i_ * 256;                                           \
            int nn_ = idx_ >> 6, k4_ = (idx_ & 63) * 4;                        \
            CP16(smem_u32(&Bs[s_][nn_][k4_]),                                  \
                 &ZT[(size_t)(nb_ + nn_) * K2 + k4_]);                         \
        }                                                                      \
        CP_COMMIT();                                                           \
    } while (0)

    #define LD_H(it_) do {                                                     \
        int nb_ = n0 + (it_) * 32;                                             \
        hv0 = *(const float4*)&Zb[(size_t)(K2 + c_) * NN + nb_ + nj_];         \
        wv0 = *(const float4*)&wszb[nb_ + nj_];                                \
        hv1 = *(const float4*)&Zb[(size_t)(K2 + c_) * NN + nb_ + nj_ + 16];    \
        wv1 = *(const float4*)&wszb[nb_ + nj_ + 16];                           \
    } while (0)

    #define ST_H(s_) do {                                                      \
        int col_ = (2 * c_) ^ sw;                                              \
        float a0_ = hv0.x*wv0.x, a1_ = hv0.y*wv0.y, a2_ = hv0.z*wv0.z, a3_ = hv0.w*wv0.w; \
        float a4_ = hv1.x*wv1.x, a5_ = hv1.y*wv1.y, a6_ = hv1.z*wv1.z, a7_ = hv1.w*wv1.w; \
        *(float2*)&Hs[s_][nj_+0][col_]  = make_float2(a0_, a0_);               \
        *(float2*)&Hs[s_][nj_+1][col_]  = make_float2(a1_, a1_);               \
        *(float2*)&Hs[s_][nj_+2][col_]  = make_float2(a2_, a2_);               \
        *(float2*)&Hs[s_][nj_+3][col_]  = make_float2(a3_, a3_);               \
        *(float2*)&Hs[s_][nj_+16][col_] = make_float2(a4_, a4_);               \
        *(float2*)&Hs[s_][nj_+17][col_] = make_float2(a5_, a5_);               \
        *(float2*)&Hs[s_][nj_+18][col_] = make_float2(a6_, a6_);               \
        *(float2*)&Hs[s_][nj_+19][col_] = make_float2(a7_, a7_);               \
    } while (0)

    ISSUE_B(0, 0);
    LD_H(0);
    ST_H(0);
    LD_H(1);
    CP_WAIT0();
    __syncthreads();

    for (int it = 0; it < 16; it++) {
        int sb = it & 1, sn = sb ^ 1;
        if (it < 15) { ISSUE_B(it + 1, sn); ST_H(sn); }
        #pragma unroll
        for (int nn = 0; nn < 32; nn++) {
            int swr = ((nn & 15) >> 2) << 4;
            int ca = (ty * 8) ^ swr;
            ulonglong2 a0 = *(const ulonglong2*)&Hs[sb][nn][ca];
            ulonglong2 a1 = *(const ulonglong2*)&Hs[sb][nn][ca + 4];
            ulonglong2 a2 = *(const ulonglong2*)&Hs[sb][nn][64 + ca];
            ulonglong2 a3 = *(const ulonglong2*)&Hs[sb][nn][64 + ca + 4];
            ulonglong2 b0 = *(const ulonglong2*)&Bs[sb][nn][tx*4];
            ulonglong2 b1 = *(const ulonglong2*)&Bs[sb][nn][128 + tx*4];
            unsigned long long av[8] = {a0.x, a0.y, a1.x, a1.y, a2.x, a2.y, a3.x, a3.y};
            unsigned long long bv[4] = {b0.x, b0.y, b1.x, b1.y};
            #pragma unroll
            for (int u = 0; u < 8; u++)
                #pragma unroll
                for (int v = 0; v < 4; v++)
                    FMA2(acc[u][v], av[u], bv[v]);
        }
        if (it < 14) LD_H(it + 2);
        if (it < 15) CP_WAIT0();
        __syncthreads();
    }
    #undef ISSUE_B
    #undef LD_H
    #undef ST_H

    float* P = g_X2p + (size_t)(b * NCHUNK + chunk) * CC * K2;
    #pragma unroll
    for (int u = 0; u < 8; u++) {
        int cu = (u < 4) ? (ty * 4 + u) : (32 + ty * 4 + u - 4);
        ulonglong2 s0; s0.x = acc[u][0]; s0.y = acc[u][1];
        ulonglong2 s1; s1.x = acc[u][2]; s1.y = acc[u][3];
        *(ulonglong2*)&P[cu * K2 + tx * 4]       = s0;
        *(ulonglong2*)&P[cu * K2 + 128 + tx * 4] = s1;
    }
}

// ---------------------------------------------------------------------------
// Low-rank mixing fused with split-K reduction — k-contiguous (coalesced).
// Grid (4 k-tiles of 32, BB), 256 threads.
// ---------------------------------------------------------------------------
__global__ void __launch_bounds__(256) k_lowrank(const float* __restrict__ wc1,
                                                 const float* __restrict__ wc2,
                                                 const float* __restrict__ ws1,
                                                 const float* __restrict__ ws2, int l) {
    int kt = blockIdx.x, b = blockIdx.y;
    int k0 = kt * 32;
    __shared__ float xc[CC][33];
    __shared__ float xs[CC][33];
    __shared__ float su[16][32];
    int t = threadIdx.x;
    int w = t >> 5, lane = t & 31;
    const float* P = g_X2p + (size_t)b * NCHUNK * CC * K2;

    // split-K reduction, coalesced: warp w handles o = j*8 + w
    #pragma unroll
    for (int j = 0; j < 8; j++) {
        int o = j * 8 + w;
        float sc = 0.f, ss = 0.f;
        #pragma unroll
        for (int ch = 0; ch < NCHUNK; ch++) {
            const float* row = P + (size_t)ch * CC * K2 + o * K2;
            sc += row[k0 + lane];
            ss += row[KK + k0 + lane];
        }
        xc[o][lane] = sc;
        xs[o][lane] = -ss;
    }
    __syncthreads();

    // u[which][r] per k: 16 combos x 32 k; each thread does 2 combos
    #pragma unroll
    for (int half = 0; half < 2; half++) {
        int combo = half * 8 + w;          // 0..15
        int which = combo >> 2, r = combo & 3;
        const float (*src)[33] = (which >> 1) ? xs : xc;
        const float* W1 = ((which & 1) ? ws1 : wc1) + (size_t)l * CC * RR * KK;
        float s = 0.f;
        #pragma unroll 8
        for (int i = 0; i < CC; i++)
            s += src[i][lane] * W1[(i * RR + r) * KK + k0 + lane];
        su[combo][lane] = s;
    }
    __syncthreads();

    // outputs, coalesced in k
    #pragma unroll
    for (int j = 0; j < 8; j++) {
        int o = j * 8 + w;
        float fc = 0.f, fs = 0.f;
        #pragma unroll
        for (int r = 0; r < RR; r++) {
            float c2v = wc2[((size_t)(l * RR + r) * CC + o) * KK + k0 + lane];
            float s2v = ws2[((size_t)(l * RR + r) * CC + o) * KK + k0 + lane];
            fc += su[r][lane]      * c2v - su[12 + r][lane] * s2v;
            fs += su[8 + r][lane]  * c2v + su[4 + r][lane]  * s2v;
        }
        g_W[(b * CC + o) * K2 + k0 + lane]      =  2.f * INVN * fc;
        g_W[(b * CC + o) * K2 + KK + k0 + lane] = -2.f * INVN * fs;
    }
}

// ---------------------------------------------------------------------------
// Inverse transform + conv + bias (+gelu) + inline f0 + next-layer x0 partials
// Tile 64c x 256n, kstep 32 (10 tiles). Double-buffered (halved barriers).
// ---------------------------------------------------------------------------
__global__ void __launch_bounds__(256, 2) k_inv(const float* __restrict__ wconv,
                                                const float* __restrict__ bconv,
                                                const float* __restrict__ w01,
                                                const float* __restrict__ w02,
                                                int l, int do_gelu) {
    int nt = blockIdx.x, b = blockIdx.y;
    int n0 = nt * 256;
    float* Zb = g_Z + (size_t)b * KW * NN;
    const float* Wb = g_W + (size_t)b * CC * K2;
    const float* wcv = wconv + l * CC * CC;
    const float* xin  = (l & 1) ? g_x0pB : g_x0pA;
    float*       xout = (l & 1) ? g_x0pA : g_x0pB;
    __shared__ float Zs[2][32][256];
    __shared__ float Ws[2][32][128];
    __shared__ float s_x0[CC];
    __shared__ float s_f0[CC];
    int t = threadIdx.x;
    int ty = t >> 5, tx = t & 31;
    int c_ = t >> 2, kj_ = (t & 3) * 4;
    int sw = kj_ << 2;
    unsigned long long acc[8][4];
    #pragma unroll
    for (int u = 0; u < 8; u++)
        #pragma unroll
        for (int v = 0; v < 4; v++) acc[u][v] = 0ULL;

    float w0, w1, w2, w3, w4, w5, w6, w7;

    #define ISSUE_Z(it_, s_) do {                                              \
        int k0_ = (it_) * 32;                                                  \
        _Pragma("unroll")                                                      \
        for (int i_ = 0; i_ < 8; i_++) {                                       \
            int idx_ = t + i_ * 256;                                           \
            int kk_ = idx_ >> 6, nl_ = (idx_ & 63) * 4;                        \
            CP16(smem_u32(&Zs[s_][kk_][nl_]),                                  \
                 &Zb[(size_t)(k0_ + kk_) * NN + n0 + nl_]);                    \
        }                                                                      \
        CP_COMMIT();                                                           \
    } while (0)

    #define LD_W(it_) do {                                                     \
        int k0_ = (it_) * 32;                                                  \
        if (k0_ < K2) {                                                        \
            float4 wa_ = *(const float4*)&Wb[c_ * K2 + k0_ + kj_];             \
            float4 wb_ = *(const float4*)&Wb[c_ * K2 + k0_ + kj_ + 16];        \
            w0 = wa_.x; w1 = wa_.y; w2 = wa_.z; w3 = wa_.w;                    \
            w4 = wb_.x; w5 = wb_.y; w6 = wb_.z; w7 = wb_.w;                    \
        } else {                                                               \
            int kq_ = k0_ + kj_ - K2;                                          \
            w0 = wcv[(kq_+0)  * CC + c_];                                      \
            w1 = wcv[(kq_+1)  * CC + c_];                                      \
            w2 = wcv[(kq_+2)  * CC + c_];                                      \
            w3 = wcv[(kq_+3)  * CC + c_];                                      \
            w4 = wcv[(kq_+16) * CC + c_];                                      \
            w5 = wcv[(kq_+17) * CC + c_];                                      \
            w6 = wcv[(kq_+18) * CC + c_];                                      \
            w7 = wcv[(kq_+19) * CC + c_];                                      \
        }                                                                      \
    } while (0)

    #define ST_W(s_) do {                                                      \
        int col_ = (2 * c_) ^ sw;                                              \
        *(float2*)&Ws[s_][kj_+0][col_]  = make_float2(w0, w0);                 \
        *(float2*)&Ws[s_][kj_+1][col_]  = make_float2(w1, w1);                 \
        *(float2*)&Ws[s_][kj_+2][col_]  = make_float2(w2, w2);                 \
        *(float2*)&Ws[s_][kj_+3][col_]  = make_float2(w3, w3);                 \
        *(float2*)&Ws[s_][kj_+16][col_] = make_float2(w4, w4);                 \
        *(float2*)&Ws[s_][kj_+17][col_] = make_float2(w5, w5);                 \
        *(float2*)&Ws[s_][kj_+18][col_] = make_float2(w6, w6);                 \
        *(float2*)&Ws[s_][kj_+19][col_] = make_float2(w7, w7);                 \
    } while (0)

    ISSUE_Z(0, 0);
    LD_W(0);
    ST_W(0);
    // phase A: x0[c] = sum of 32 partials (t < 64)
    if (t < CC) {
        float s = 0.f;
        #pragma unroll
        for (int ch = 0; ch < 32; ch++) s += xin[(b * 32 + ch) * CC + t];
        s_x0[t] = s;
    }
    LD_W(1);
    CP_WAIT0();
    __syncthreads();
    // phase B: f0[o] = rank-4 contraction of s_x0 (t < 64); visible after next bar
    if (t < CC) {
        float f = 0.f;
        #pragma unroll
        for (int r = 0; r < RR; r++) {
            float uu = 0.f;
            #pragma unroll 8
            for (int i = 0; i < CC; i++) uu += s_x0[i] * w01[(l * CC + i) * RR + r];
            f += uu * w02[(l * RR + r) * CC + t];
        }
        s_f0[t] = f * INVN;
    }

    for (int it = 0; it < 10; it++) {
        int sb = it & 1, sn = sb ^ 1;
        if (it < 9) { ISSUE_Z(it + 1, sn); ST_W(sn); }
        #pragma unroll
        for (int kk = 0; kk < 32; kk++) {
            int swr = ((kk & 15) >> 2) << 4;
            int ca = (ty * 8) ^ swr;
            ulonglong2 a0 = *(const ulonglong2*)&Ws[sb][kk][ca];
            ulonglong2 a1 = *(const ulonglong2*)&Ws[sb][kk][ca + 4];
            ulonglong2 a2 = *(const ulonglong2*)&Ws[sb][kk][64 + ca];
            ulonglong2 a3 = *(const ulonglong2*)&Ws[sb][kk][64 + ca + 4];
            ulonglong2 b0 = *(const ulonglong2*)&Zs[sb][kk][tx*4];
            ulonglong2 b1 = *(const ulonglong2*)&Zs[sb][kk][128 + tx*4];
            unsigned long long av[8] = {a0.x, a0.y, a1.x, a1.y, a2.x, a2.y, a3.x, a3.y};
            unsigned long long bv[4] = {b0.x, b0.y, b1.x, b1.y};
            #pragma unroll
            for (int u = 0; u < 8; u++)
                #pragma unroll
                for (int v = 0; v < 4; v++)
                    FMA2(acc[u][v], av[u], bv[v]);
        }
        if (it < 8) LD_W(it + 2);
        if (it < 9) CP_WAIT0();
        __syncthreads();
    }
    #undef ISSUE_Z
    #undef LD_W
    #undef ST_W

    float4 mk4[2], mw4[2];
    #pragma unroll
    for (int half = 0; half < 2; half++) {
        int nb = n0 + half * 128 + tx * 4;
        mk4[half] = *(const float4*)&g_mask[b * NN + nb];
        mw4[half] = *(const float4*)&g_mw[b * NN + nb];
    }
    float p[8];
    #pragma unroll
    for (int u = 0; u < 8; u++) p[u] = 0.f;
    #pragma unroll
    for (int u = 0; u < 8; u++) {
        int c = (u < 4) ? (ty * 4 + u) : (32 + ty * 4 + u - 4);
        float f0v = s_f0[c];
        float bcv = bconv[l * CC + c];
        float ov[8];
        #pragma unroll
        for (int v = 0; v < 4; v++) {
            float lo, hi;
            UNPACKF2(lo, hi, acc[u][v]);
            ov[2*v] = lo; ov[2*v+1] = hi;
        }
        #pragma unroll
        for (int half = 0; half < 2; half++) {
            int nb = n0 + half * 128 + tx * 4;
            const float* mkp = (const float*)&mk4[half];
            const float* mwp = (const float*)&mw4[half];
            float r[4];
            #pragma unroll
            for (int j = 0; j < 4; j++) {
                float val = ov[half*4 + j] + f0v * mkp[j] + bcv;
                if (do_gelu) val = GELU(val);
                r[j] = val;
                p[u] += val * mwp[j];
            }
            *(float4*)&Zb[(size_t)(K2 + c) * NN + nb] = make_float4(r[0], r[1], r[2], r[3]);
        }
    }
    if (do_gelu) {
        #pragma unroll
        for (int u = 0; u < 8; u++) {
            float s = p[u];
            #pragma unroll
            for (int o = 16; o > 0; o >>= 1) s += __shfl_down_sync(0xffffffffu, s, o);
            if (tx == 0) {
                int c = (u < 4) ? (ty * 4 + u) : (32 + ty * 4 + u - 4);
                xout[(b * 32 + nt) * CC + c] = s;
            }
        }
    }
}

// Final MLP: out = fc2(gelu(fc1(h))); j-block 32 (packs hoisted 4x).
__global__ void __launch_bounds__(256) k_mlp(const float* __restrict__ w1,
                                             const float* __restrict__ b1,
                                             const float* __restrict__ w2,
                                             const float* __restrict__ b2,
                                             float* __restrict__ out) {
    __shared__ float Wsm[CC * 128];
    __shared__ float b1s[128], w2s[128];
    int t = threadIdx.x;
    for (int i = t; i < CC * 128; i += 256) Wsm[i] = w1[i];
    if (t < 128) { b1s[t] = b1[t]; w2s[t] = w2[t]; }
    __syncthreads();
    int b = blockIdx.y;
    int n = blockIdx.x * 256 + t;
    const float* Zb = g_Z + (size_t)b * KW * NN;
    float h[CC];
    #pragma unroll
    for (int c = 0; c < CC; c++) h[c] = Zb[(size_t)(K2 + c) * NN + n];
    float acc = b2[0];
    for (int j0 = 0; j0 < 128; j0 += 32) {
        unsigned long long a[16];
        #pragma unroll
        for (int q = 0; q < 16; q++)
            PACKF2(a[q], b1s[j0 + 2*q], b1s[j0 + 2*q + 1]);
        #pragma unroll
        for (int c = 0; c < CC; c++) {
            unsigned long long hd;
            PACKF2(hd, h[c], h[c]);
            const float* wr = &Wsm[c * 128 + j0];
            #pragma unroll
            for (int q8 = 0; q8 < 4; q8++) {
                ulonglong2 wv = *(const ulonglong2*)(wr + q8 * 8);
                ulonglong2 wv2 = *(const ulonglong2*)(wr + q8 * 8 + 4);
                FMA2(a[q8*4 + 0], hd, wv.x);
                FMA2(a[q8*4 + 1], hd, wv.y);
                FMA2(a[q8*4 + 2], hd, wv2.x);
                FMA2(a[q8*4 + 3], hd, wv2.y);
            }
        }
        #pragma unroll
        for (int q = 0; q < 16; q++) {
            float lo, hi;
            UNPACKF2(lo, hi, a[q]);
            acc += GELU(lo) * w2s[j0 + 2*q];
            acc += GELU(hi) * w2s[j0 + 2*q + 1];
        }
    }
    out[(size_t)b * NN + n] = acc;
}

extern "C" void kernel_launch(void* const* d_in, const int* in_sizes, int n_in,
                              void* d_out, int out_size) {
    const float* x    = (const float*)d_in[0];
    const float* fc0w = (const float*)d_in[1];
    const float* fc0b = (const float*)d_in[2];
    const float* wc1  = (const float*)d_in[3];
    const float* wc2  = (const float*)d_in[4];
    const float* ws1  = (const float*)d_in[5];
    const float* ws2  = (const float*)d_in[6];
    const float* w01  = (const float*)d_in[7];
    const float* w02  = (const float*)d_in[8];
    const float* wconv = (const float*)d_in[9];
    const float* bconv = (const float*)d_in[10];
    const float* fc1w = (const float*)d_in[11];
    const float* fc1b = (const float*)d_in[12];
    const float* fc2w = (const float*)d_in[13];
    const float* fc2b = (const float*)d_in[14];
    float* out = (float*)d_out;

    k_pre<<<BB * NN / 256, 256>>>(x, fc0w, fc0b);
    k_tr<<<dim3(NN / 32, K2 / 32, BB), 256>>>();
    k_x0p32<<<dim3(32, BB), 256>>>();
    for (int l = 0; l < NL; l++) {
        k_fwd<<<dim3(NCHUNK, BB), 256>>>();
        k_lowrank<<<dim3(4, BB), 256>>>(wc1, wc2, ws1, ws2, l);
        k_inv<<<dim3(NN / 256, BB), 256>>>(wconv, bconv, w01, w02, l,
                                           (l != NL - 1) ? 1 : 0);
    }
    k_mlp<<<dim3(NN / 256, BB), 256>>>(fc1w, fc1b, fc2w, fc2b, out);
}